// round 1
// baseline (speedup 1.0000x reference)
#include <cuda_runtime.h>
#include <math.h>

#define PI_F 3.14159265358979323846f

__device__ __forceinline__ float2 cmul(float2 a, float2 b) {
    return make_float2(a.x*b.x - a.y*b.y, a.x*b.y + a.y*b.x);
}
__device__ __forceinline__ float2 cadd(float2 a, float2 b) {
    return make_float2(a.x + b.x, a.y + b.y);
}

// Block: 128 threads, 64 rows. Phase 1: warp-per-row GEMV (each warp 16 rows).
// Phase 2: thread-per-row 16-dim statevector simulation, fully in registers.
__global__ __launch_bounds__(128)
void qrnn_cell_kernel(const float* __restrict__ inputs,   // (B, 512)
                      const float* __restrict__ prev_h,   // (B, 4)
                      const float* __restrict__ W_enc,    // (516, 4)
                      const float* __restrict__ b_enc,    // (4,)
                      const float* __restrict__ theta,    // (2, 4, 3)
                      const float* __restrict__ W_out,    // (4, 4)
                      const float* __restrict__ b_out,    // (4,)
                      float* __restrict__ out,            // (B, 4)
                      int B)
{
    __shared__ float2 sU[8][4];       // fused U = RY*RZ*RX per (l,q): [u00,u01,u10,u11]
    __shared__ float  sWtail[4][4];   // W_enc rows 512..515 (prev_h part)
    __shared__ float  sWout[16];
    __shared__ float  sbenc[4];
    __shared__ float  sbout[4];
    __shared__ float4 sPre[64];       // raw dot products per local row

    const int tid  = threadIdx.x;
    const int lane = tid & 31;
    const int wid  = tid >> 5;
    const int rowbase = blockIdx.x * 64;

    // ---------------- setup: fused gate matrices (batch-independent) ------------
    if (tid < 8) {
        int l = tid >> 2, q = tid & 3;
        const float* th = theta + (l * 4 + q) * 3;
        float ca, sa, cb, sb, cy, sy;
        sincosf(0.5f * th[0], &sa, &ca);
        sincosf(0.5f * th[1], &sb, &cb);
        sincosf(0.5f * th[2], &sy, &cy);
        // RX = [[ca, -i sa], [-i sa, ca]]
        float2 RX0 = make_float2(ca, 0.f),  RX1 = make_float2(0.f, -sa);
        float2 RX2 = make_float2(0.f, -sa), RX3 = make_float2(ca, 0.f);
        // RZ = diag(e^{-ib}, e^{ib})
        float2 RZ0 = make_float2(cb, -sb), RZ3 = make_float2(cb, sb);
        // RY = [[cy, -sy], [sy, cy]]
        // M = RZ * RX (RZ diagonal)
        float2 M0 = cmul(RZ0, RX0);
        float2 M1 = cmul(RZ0, RX1);
        float2 M2 = cmul(RZ3, RX2);
        float2 M3 = cmul(RZ3, RX3);
        // U = RY * M
        sU[tid][0] = cadd(make_float2(cy * M0.x, cy * M0.y), make_float2(-sy * M2.x, -sy * M2.y));
        sU[tid][1] = cadd(make_float2(cy * M1.x, cy * M1.y), make_float2(-sy * M3.x, -sy * M3.y));
        sU[tid][2] = cadd(make_float2(sy * M0.x, sy * M0.y), make_float2( cy * M2.x,  cy * M2.y));
        sU[tid][3] = cadd(make_float2(sy * M1.x, sy * M1.y), make_float2( cy * M3.x,  cy * M3.y));
    }
    if (tid < 4) {
        sbenc[tid] = b_enc[tid];
        sbout[tid] = b_out[tid];
        #pragma unroll
        for (int j = 0; j < 4; j++)
            sWtail[tid][j] = W_enc[(512 + tid) * 4 + j];
    }
    if (tid >= 8 && tid < 24) sWout[tid - 8] = W_out[tid - 8];

    // ---------------- phase 1: 512-wide dot products (warp-cooperative) ---------
    const float4* in4 = reinterpret_cast<const float4*>(inputs);
    const float4* w4  = reinterpret_cast<const float4*>(W_enc);

    // Preload this lane's 16 W_enc rows (k = 4*lane + 128*t + e) into registers.
    float4 wreg[16];
    #pragma unroll
    for (int t = 0; t < 4; t++)
        #pragma unroll
        for (int e = 0; e < 4; e++)
            wreg[t * 4 + e] = w4[4 * lane + 128 * t + e];

    #pragma unroll 2
    for (int it = 0; it < 8; it++) {
        int lr0 = wid * 16 + 2 * it;
        long r0 = (long)rowbase + lr0;
        long r0c = (r0 + 1 < B) ? r0 : (long)(B >= 2 ? B - 2 : 0);  // clamp (safety)
        const float4* p0 = in4 + r0c * 128;
        const float4* p1 = p0 + 128;

        float xa[16], xb[16];
        #pragma unroll
        for (int t = 0; t < 4; t++) {
            float4 v0 = p0[lane + 32 * t];
            float4 v1 = p1[lane + 32 * t];
            xa[4*t+0] = v0.x; xa[4*t+1] = v0.y; xa[4*t+2] = v0.z; xa[4*t+3] = v0.w;
            xb[4*t+0] = v1.x; xb[4*t+1] = v1.y; xb[4*t+2] = v1.z; xb[4*t+3] = v1.w;
        }

        float a0[4] = {0.f, 0.f, 0.f, 0.f};
        float a1[4] = {0.f, 0.f, 0.f, 0.f};
        #pragma unroll
        for (int k = 0; k < 16; k++) {
            float4 w = wreg[k];
            a0[0] = fmaf(xa[k], w.x, a0[0]);
            a0[1] = fmaf(xa[k], w.y, a0[1]);
            a0[2] = fmaf(xa[k], w.z, a0[2]);
            a0[3] = fmaf(xa[k], w.w, a0[3]);
            a1[0] = fmaf(xb[k], w.x, a1[0]);
            a1[1] = fmaf(xb[k], w.y, a1[1]);
            a1[2] = fmaf(xb[k], w.z, a1[2]);
            a1[3] = fmaf(xb[k], w.w, a1[3]);
        }
        #pragma unroll
        for (int off = 16; off > 0; off >>= 1) {
            #pragma unroll
            for (int j = 0; j < 4; j++) {
                a0[j] += __shfl_xor_sync(0xffffffffu, a0[j], off);
                a1[j] += __shfl_xor_sync(0xffffffffu, a1[j], off);
            }
        }
        if (lane == 0) {
            sPre[lr0]     = make_float4(a0[0], a0[1], a0[2], a0[3]);
            sPre[lr0 + 1] = make_float4(a1[0], a1[1], a1[2], a1[3]);
        }
    }
    __syncthreads();

    // ---------------- phase 2: per-row quantum circuit in registers -------------
    if (tid < 64) {
        int row = rowbase + tid;
        if (row < B) {
            float4 pre = sPre[tid];
            float4 ph  = reinterpret_cast<const float4*>(prev_h)[row];
            float acc[4] = {pre.x, pre.y, pre.z, pre.w};
            #pragma unroll
            for (int j = 0; j < 4; j++) {
                acc[j] += sbenc[j]
                        + ph.x * sWtail[0][j] + ph.y * sWtail[1][j]
                        + ph.z * sWtail[2][j] + ph.w * sWtail[3][j];
            }
            // half-angles of RY encodings: tanh(.)*pi*0.5, in [-pi/2, pi/2]
            float cv[4], sv[4];
            #pragma unroll
            for (int q = 0; q < 4; q++) {
                float half = tanhf(acc[q]) * (0.5f * PI_F);
                __sincosf(half, &sv[q], &cv[q]);
            }
            // product state: qubit q's bit of index i is (i >> (3-q)) & 1
            float sr[16], si[16];
            #pragma unroll
            for (int i = 0; i < 16; i++) {
                float v = ((i & 8) ? sv[0] : cv[0])
                        * ((i & 4) ? sv[1] : cv[1])
                        * ((i & 2) ? sv[2] : cv[2])
                        * ((i & 1) ? sv[3] : cv[3]);
                sr[i] = v;
                si[i] = 0.f;
            }
            // L=2 layers: fused 1q gate per qubit, then CNOT chain
            #pragma unroll
            for (int l = 0; l < 2; l++) {
                #pragma unroll
                for (int q = 0; q < 4; q++) {
                    float2 u00 = sU[l*4+q][0];
                    float2 u01 = sU[l*4+q][1];
                    float2 u10 = sU[l*4+q][2];
                    float2 u11 = sU[l*4+q][3];
                    const int m = 8 >> q;
                    #pragma unroll
                    for (int i = 0; i < 16; i++) {
                        if (i & m) continue;
                        const int i1 = i | m;
                        float ar = sr[i],  ai = si[i];
                        float br = sr[i1], bi = si[i1];
                        sr[i]  = u00.x*ar - u00.y*ai + u01.x*br - u01.y*bi;
                        si[i]  = u00.x*ai + u00.y*ar + u01.x*bi + u01.y*br;
                        sr[i1] = u10.x*ar - u10.y*ai + u11.x*br - u11.y*bi;
                        si[i1] = u10.x*ai + u10.y*ar + u11.x*bi + u11.y*br;
                    }
                }
                #pragma unroll
                for (int q = 0; q < 3; q++) {
                    const int mc = 8 >> q, mt = 4 >> q;
                    #pragma unroll
                    for (int i = 0; i < 16; i++) {
                        if ((i & mc) && !(i & mt)) {
                            const int i1 = i | mt;
                            float tr = sr[i]; sr[i] = sr[i1]; sr[i1] = tr;
                            float ti = si[i]; si[i] = si[i1]; si[i1] = ti;
                        }
                    }
                }
            }
            // PauliZ expectations
            float ev[4] = {0.f, 0.f, 0.f, 0.f};
            #pragma unroll
            for (int i = 0; i < 16; i++) {
                float p = sr[i]*sr[i] + si[i]*si[i];
                ev[0] += (i & 8) ? -p : p;
                ev[1] += (i & 4) ? -p : p;
                ev[2] += (i & 2) ? -p : p;
                ev[3] += (i & 1) ? -p : p;
            }
            // next_h = tanh(ev @ W_out + b_out)
            float4 o;
            o.x = tanhf(ev[0]*sWout[0] + ev[1]*sWout[4] + ev[2]*sWout[8]  + ev[3]*sWout[12] + sbout[0]);
            o.y = tanhf(ev[0]*sWout[1] + ev[1]*sWout[5] + ev[2]*sWout[9]  + ev[3]*sWout[13] + sbout[1]);
            o.z = tanhf(ev[0]*sWout[2] + ev[1]*sWout[6] + ev[2]*sWout[10] + ev[3]*sWout[14] + sbout[2]);
            o.w = tanhf(ev[0]*sWout[3] + ev[1]*sWout[7] + ev[2]*sWout[11] + ev[3]*sWout[15] + sbout[3]);
            reinterpret_cast<float4*>(out)[row] = o;
        }
    }
}

extern "C" void kernel_launch(void* const* d_in, const int* in_sizes, int n_in,
                              void* d_out, int out_size)
{
    const float* inputs = (const float*)d_in[0];
    const float* prev_h = (const float*)d_in[1];
    const float* W_enc  = (const float*)d_in[2];
    const float* b_enc  = (const float*)d_in[3];
    const float* theta  = (const float*)d_in[4];
    const float* W_out  = (const float*)d_in[5];
    const float* b_out  = (const float*)d_in[6];

    int B = in_sizes[0] / 512;
    int grid = (B + 63) / 64;
    qrnn_cell_kernel<<<grid, 128>>>(inputs, prev_h, W_enc, b_enc, theta,
                                    W_out, b_out, (float*)d_out, B);
}